// round 5
// baseline (speedup 1.0000x reference)
#include <cuda_runtime.h>

// ----------------------------------------------------------------------------
// HadamardProj — the reference "fwht" butterflies the LSB pair every stage
// with no stride growth, so S^2 = 2I and S^10 * d^-0.5 = 32I/32 = identity.
// reference(x, scales) == x * (s0*s1*s2*s3*s4)[d]  (elementwise, broadcast on D).
// Pure memory-bound elementwise scale: 64 MiB in + 64 MiB out.
// ----------------------------------------------------------------------------

#define D 1024
#define N_SCALES 5

__device__ float g_combined[D];  // folded per-column scale product (4 KB)

__global__ void combine_scales_kernel(const float* __restrict__ scales) {
    int d = blockIdx.x * blockDim.x + threadIdx.x;
    if (d < D) {
        float p = scales[d];
        #pragma unroll
        for (int i = 1; i < N_SCALES; ++i) p *= scales[i * D + d];
        g_combined[d] = p;
    }
}

__global__ void __launch_bounds__(256) scale_kernel(
    const float4* __restrict__ x, float4* __restrict__ out, int n4
) {
    int i = blockIdx.x * blockDim.x + threadIdx.x;
    if (i < n4) {
        // 256 float4s per D-row; scale vector is a guaranteed L1 hit after warmup.
        const float4* __restrict__ c4 = reinterpret_cast<const float4*>(g_combined);
        float4 s = c4[i & (D / 4 - 1)];
        float4 v = x[i];
        v.x *= s.x;
        v.y *= s.y;
        v.z *= s.z;
        v.w *= s.w;
        out[i] = v;
    }
}

extern "C" void kernel_launch(void* const* d_in, const int* in_sizes, int n_in,
                              void* d_out, int out_size) {
    const float* x      = (const float*)d_in[0];   // (4, 4096, 1024) fp32
    const float* scales = (const float*)d_in[1];   // (5, 1024) fp32
    float* out = (float*)d_out;

    int n  = in_sizes[0];      // 16,777,216
    int n4 = n / 4;            // 4,194,304 float4s

    combine_scales_kernel<<<(D + 255) / 256, 256>>>(scales);

    int threads = 256;
    int blocks  = (n4 + threads - 1) / threads;    // 16384
    scale_kernel<<<blocks, threads>>>(
        reinterpret_cast<const float4*>(x),
        reinterpret_cast<float4*>(out),
        n4);
}

// round 7
// speedup vs baseline: 1.2931x; 1.2931x over previous
#include <cuda_runtime.h>

// ----------------------------------------------------------------------------
// HadamardProj — reference "fwht" butterflies the LSB pair every stage with no
// stride growth: S^2 = 2I, S^10 * d^-0.5 = identity. So:
//   reference(x, scales) == x * (s0*s1*s2*s3*s4)  (elementwise, broadcast on D)
//
// Single fused kernel. Block = 256 threads covering 1024 contiguous float4
// (= 4 rows of D=1024 floats). Thread t's column group is exactly t for all
// its 4 elements, so the 5-row scale fold is 5 cached float4 loads (L1-hot
// after the first CTA per SM). Front-batched x loads (MLP=4/thread) and
// streaming stores (__stcs) so the write stream doesn't evict x from L2
// across graph replays.
// ----------------------------------------------------------------------------

#define D 1024
#define N_SCALES 5
#define VPT 4                     // float4s per thread
#define TPB 256                   // threads per block
#define F4_PER_BLOCK (TPB * VPT)  // 1024 float4 = 4 D-rows

__global__ void __launch_bounds__(TPB) fused_scale_kernel(
    const float4* __restrict__ x,
    const float4* __restrict__ scales4,   // (5, 256) float4
    float4* __restrict__ out,
    int n4)
{
    const int t = threadIdx.x;

    // Fold the 5 scale rows for this thread's column group (cols 4t..4t+3).
    float4 s = __ldg(&scales4[t]);
    #pragma unroll
    for (int i = 1; i < N_SCALES; ++i) {
        float4 si = __ldg(&scales4[i * (D / 4) + t]);
        s.x *= si.x; s.y *= si.y; s.z *= si.z; s.w *= si.w;
    }

    const int base = blockIdx.x * F4_PER_BLOCK + t;

    // Front-batch the 4 independent 128-bit loads (MLP_p1 = 4).
    float4 v[VPT];
    #pragma unroll
    for (int k = 0; k < VPT; ++k) {
        int idx = base + k * TPB;
        if (idx < n4) v[k] = x[idx];
    }

    #pragma unroll
    for (int k = 0; k < VPT; ++k) {
        int idx = base + k * TPB;
        if (idx < n4) {
            v[k].x *= s.x; v[k].y *= s.y; v[k].z *= s.z; v[k].w *= s.w;
            __stcs(&out[idx], v[k]);   // evict-first: keep x resident in L2
        }
    }
}

extern "C" void kernel_launch(void* const* d_in, const int* in_sizes, int n_in,
                              void* d_out, int out_size) {
    const float* x      = (const float*)d_in[0];   // (4, 4096, 1024) fp32
    const float* scales = (const float*)d_in[1];   // (5, 1024) fp32
    float* out = (float*)d_out;

    int n  = in_sizes[0];          // 16,777,216 floats
    int n4 = n / 4;                // 4,194,304 float4s

    int blocks = (n4 + F4_PER_BLOCK - 1) / F4_PER_BLOCK;   // 4096
    fused_scale_kernel<<<blocks, TPB>>>(
        reinterpret_cast<const float4*>(x),
        reinterpret_cast<const float4*>(scales),
        reinterpret_cast<float4*>(out),
        n4);
}